// round 1
// baseline (speedup 1.0000x reference)
#include <cuda_runtime.h>
#include <cstdint>

#define BB 4
#define SS 4096
#define DIN 1024
#define DOUT 64

// Scratch for projected q,k,v (allocation-free rule: __device__ globals).
__device__ float g_q[BB * SS * DOUT];
__device__ float g_k[BB * SS * DOUT];
__device__ float g_v[BB * SS * DOUT];

// ---------------------------------------------------------------------------
// Projection: out[r][n] = sum_k x[r][k] * W[n][k]   (torch Linear: x @ W^T)
// Tile: 64 (M) x 64 (N=DOUT) x 16 (K). 256 threads, 4x4 microtile each.
// blockIdx.y selects which of Wq/Wk/Wv.
// ---------------------------------------------------------------------------
__global__ __launch_bounds__(256) void proj_kernel(
    const float* __restrict__ x,
    const float* __restrict__ Wq,
    const float* __restrict__ Wk,
    const float* __restrict__ Wv)
{
    __shared__ float Xs[16][64];
    __shared__ float Ws[16][64];

    const int widx = blockIdx.y;
    const float* __restrict__ W = (widx == 0) ? Wq : (widx == 1) ? Wk : Wv;
    float* __restrict__ out = (widx == 0) ? g_q : (widx == 1) ? g_k : g_v;

    const int m0  = blockIdx.x * 64;
    const int tid = threadIdx.x;
    const int tx  = tid & 15;   // N direction
    const int ty  = tid >> 4;   // M direction

    const int lm = tid >> 2;          // 0..63 (row for loads)
    const int lk = (tid & 3) * 4;     // 0,4,8,12 (k sub-offset, float4)

    float acc[4][4] = {};

    for (int k0 = 0; k0 < DIN; k0 += 16) {
        // Load X tile [64m x 16k] and W tile [64n x 16k], transposed to k-major.
        float4 xv = *(const float4*)&x[(size_t)(m0 + lm) * DIN + k0 + lk];
        float4 wv = *(const float4*)&W[(size_t)lm * DIN + k0 + lk];
        Xs[lk + 0][lm] = xv.x; Xs[lk + 1][lm] = xv.y;
        Xs[lk + 2][lm] = xv.z; Xs[lk + 3][lm] = xv.w;
        Ws[lk + 0][lm] = wv.x; Ws[lk + 1][lm] = wv.y;
        Ws[lk + 2][lm] = wv.z; Ws[lk + 3][lm] = wv.w;
        __syncthreads();

        #pragma unroll
        for (int kk = 0; kk < 16; kk++) {
            float4 a = *(const float4*)&Xs[kk][ty * 4];
            float4 b = *(const float4*)&Ws[kk][tx * 4];
            float av[4] = {a.x, a.y, a.z, a.w};
            float bv[4] = {b.x, b.y, b.z, b.w};
            #pragma unroll
            for (int i = 0; i < 4; i++)
                #pragma unroll
                for (int j = 0; j < 4; j++)
                    acc[i][j] += av[i] * bv[j];
        }
        __syncthreads();
    }

    #pragma unroll
    for (int i = 0; i < 4; i++) {
        float4 o = make_float4(acc[i][0], acc[i][1], acc[i][2], acc[i][3]);
        *(float4*)&out[(size_t)(m0 + ty * 4 + i) * DOUT + tx * 4] = o;
    }
}

// ---------------------------------------------------------------------------
// Flash attention (fp32, online softmax).
// BLOCK_M = 64 queries per CTA, BLOCK_N = 64 keys per iteration, D = 64.
// 256 threads, 4x4 microtile in both GEMMs. Q pre-scaled by 1/sqrt(D).
// Smem (dynamic, 68608 B):
//   Qs[64][68] d-major, Ks[64][68] d-major, Vs[64][64] n-major, Ps[64][68] m-major
// ---------------------------------------------------------------------------
#define QK_PAD 68
#define SMEM_BYTES ((3 * 64 * QK_PAD + 64 * 64) * 4)

__global__ __launch_bounds__(256, 2) void attn_kernel(float* __restrict__ out)
{
    extern __shared__ float sm[];
    float* Qs = sm;                    // [64][68]
    float* Ks = Qs + 64 * QK_PAD;      // [64][68]
    float* Vs = Ks + 64 * QK_PAD;      // [64][64]
    float* Ps = Vs + 64 * 64;          // [64][68]

    const int b  = blockIdx.y;
    const int qb = gridDim.x - 1 - blockIdx.x;   // biggest work first
    const int q0 = qb * 64;

    const int tid = threadIdx.x;
    const int tx  = tid & 15;
    const int ty  = tid >> 4;

    const float* __restrict__ qptr  = g_q + ((size_t)b * SS + q0) * DOUT;
    const float* __restrict__ kbase = g_k + (size_t)b * SS * DOUT;
    const float* __restrict__ vbase = g_v + (size_t)b * SS * DOUT;

    const int lm = tid >> 2;          // 0..63
    const int ld = (tid & 3) * 16;    // 0,16,32,48

    // Load Q (transposed to d-major), pre-scaled by 1/sqrt(64) = 0.125
    #pragma unroll
    for (int c = 0; c < 4; c++) {
        float4 v = *(const float4*)&qptr[lm * DOUT + ld + c * 4];
        Qs[(ld + c * 4 + 0) * QK_PAD + lm] = v.x * 0.125f;
        Qs[(ld + c * 4 + 1) * QK_PAD + lm] = v.y * 0.125f;
        Qs[(ld + c * 4 + 2) * QK_PAD + lm] = v.z * 0.125f;
        Qs[(ld + c * 4 + 3) * QK_PAD + lm] = v.w * 0.125f;
    }

    float accO[4][4] = {};
    float mrow[4] = {-1e30f, -1e30f, -1e30f, -1e30f};
    float lrow[4] = {0.f, 0.f, 0.f, 0.f};

    for (int kb = 0; kb <= qb; kb++) {
        const int k0 = kb * 64;
        __syncthreads();   // prior PV done reading Vs/Ps

        // Load K tile (transposed) and V tile (natural layout)
        const float* ksrc = kbase + (size_t)k0 * DOUT;
        #pragma unroll
        for (int c = 0; c < 4; c++) {
            float4 v = *(const float4*)&ksrc[lm * DOUT + ld + c * 4];
            Ks[(ld + c * 4 + 0) * QK_PAD + lm] = v.x;
            Ks[(ld + c * 4 + 1) * QK_PAD + lm] = v.y;
            Ks[(ld + c * 4 + 2) * QK_PAD + lm] = v.z;
            Ks[(ld + c * 4 + 3) * QK_PAD + lm] = v.w;
        }
        const float4* vsrc = (const float4*)(vbase + (size_t)k0 * DOUT);
        #pragma unroll
        for (int c = 0; c < 4; c++)
            ((float4*)Vs)[tid + c * 256] = vsrc[tid + c * 256];
        __syncthreads();

        // S = (Q/8) K^T  — 4x4 microtile
        float accS[4][4] = {};
        #pragma unroll 8
        for (int d = 0; d < 64; d++) {
            float4 a = *(const float4*)&Qs[d * QK_PAD + ty * 4];
            float4 bk = *(const float4*)&Ks[d * QK_PAD + tx * 4];
            float av[4] = {a.x, a.y, a.z, a.w};
            float bv[4] = {bk.x, bk.y, bk.z, bk.w};
            #pragma unroll
            for (int i = 0; i < 4; i++)
                #pragma unroll
                for (int j = 0; j < 4; j++)
                    accS[i][j] += av[i] * bv[j];
        }

        // Causal mask (diagonal tile only)
        if (kb == qb) {
            #pragma unroll
            for (int i = 0; i < 4; i++) {
                int qi = q0 + ty * 4 + i;
                #pragma unroll
                for (int j = 0; j < 4; j++) {
                    int kj = k0 + tx * 4 + j;
                    if (kj > qi) accS[i][j] = -1e30f;
                }
            }
        }

        // Online softmax per row (row group = 16 lanes within half-warp)
        #pragma unroll
        for (int i = 0; i < 4; i++) {
            float rmax = fmaxf(fmaxf(accS[i][0], accS[i][1]),
                               fmaxf(accS[i][2], accS[i][3]));
            #pragma unroll
            for (int off = 8; off >= 1; off >>= 1)
                rmax = fmaxf(rmax, __shfl_xor_sync(0xffffffffu, rmax, off));

            float mnew = fmaxf(mrow[i], rmax);
            float corr = __expf(mrow[i] - mnew);
            float rsum = 0.f;
            #pragma unroll
            for (int j = 0; j < 4; j++) {
                float p = __expf(accS[i][j] - mnew);
                accS[i][j] = p;
                rsum += p;
            }
            #pragma unroll
            for (int off = 8; off >= 1; off >>= 1)
                rsum += __shfl_xor_sync(0xffffffffu, rsum, off);

            lrow[i] = lrow[i] * corr + rsum;
            mrow[i] = mnew;
            #pragma unroll
            for (int j = 0; j < 4; j++)
                accO[i][j] *= corr;

            // store P row segment (m-major), float4
            float4 p4 = make_float4(accS[i][0], accS[i][1], accS[i][2], accS[i][3]);
            *(float4*)&Ps[(ty * 4 + i) * QK_PAD + tx * 4] = p4;
        }
        __syncthreads();   // Ps visible; scores done with Ks

        // O += P V  — 4x4 microtile over (m, d)
        #pragma unroll 4
        for (int n = 0; n < 64; n++) {
            float4 bv4 = *(const float4*)&Vs[n * 64 + tx * 4];
            float bv[4] = {bv4.x, bv4.y, bv4.z, bv4.w};
            #pragma unroll
            for (int i = 0; i < 4; i++) {
                float a = Ps[(ty * 4 + i) * QK_PAD + n];
                #pragma unroll
                for (int j = 0; j < 4; j++)
                    accO[i][j] += a * bv[j];
            }
        }
    }

    // Normalize and store
    #pragma unroll
    for (int i = 0; i < 4; i++) {
        float inv = 1.0f / lrow[i];
        float4 o = make_float4(accO[i][0] * inv, accO[i][1] * inv,
                               accO[i][2] * inv, accO[i][3] * inv);
        *(float4*)&out[((size_t)b * SS + q0 + ty * 4 + i) * DOUT + tx * 4] = o;
    }
}

// ---------------------------------------------------------------------------
extern "C" void kernel_launch(void* const* d_in, const int* in_sizes, int n_in,
                              void* d_out, int out_size)
{
    const float* x  = (const float*)d_in[0];
    const float* Wq = (const float*)d_in[1];
    const float* Wk = (const float*)d_in[2];
    const float* Wv = (const float*)d_in[3];
    float* out = (float*)d_out;

    // QKV projections: grid (M/64, 3)
    proj_kernel<<<dim3((BB * SS) / 64, 3), 256>>>(x, Wq, Wk, Wv);

    // Flash attention: grid (S/64, B), dynamic smem > 48KB
    cudaFuncSetAttribute(attn_kernel,
                         cudaFuncAttributeMaxDynamicSharedMemorySize,
                         SMEM_BYTES);
    attn_kernel<<<dim3(SS / 64, BB), 256, SMEM_BYTES>>>(out);
}

// round 2
// speedup vs baseline: 3.5271x; 3.5271x over previous
#include <cuda_runtime.h>
#include <cstdint>

#define BB 4
#define SS 4096
#define DIN 1024
#define DOUT 64

// Scratch for projected q,k,v (allocation-free rule: __device__ globals).
__device__ float g_q[BB * SS * DOUT];
__device__ float g_k[BB * SS * DOUT];
__device__ float g_v[BB * SS * DOUT];

// ---------------------------------------------------------------------------
// Helpers
// ---------------------------------------------------------------------------
__device__ __forceinline__ uint32_t f2tf(float f) {
    uint32_t r; asm("cvt.rna.tf32.f32 %0, %1;" : "=r"(r) : "f"(f)); return r;
}
__device__ __forceinline__ float ex2(float x) {
    float r; asm("ex2.approx.f32 %0, %1;" : "=f"(r) : "f"(x)); return r;
}
__device__ __forceinline__ void mma_tf32(float c[4],
    uint32_t a0, uint32_t a1, uint32_t a2, uint32_t a3,
    uint32_t b0, uint32_t b1)
{
    asm volatile(
        "mma.sync.aligned.m16n8k8.row.col.f32.tf32.tf32.f32 "
        "{%0,%1,%2,%3}, {%4,%5,%6,%7}, {%8,%9}, {%0,%1,%2,%3};"
        : "+f"(c[0]), "+f"(c[1]), "+f"(c[2]), "+f"(c[3])
        : "r"(a0), "r"(a1), "r"(a2), "r"(a3), "r"(b0), "r"(b1));
}

// ---------------------------------------------------------------------------
// Fused QKV projection: q|k|v[m][n] = sum_k x[m][k] * W{q,k,v}[n][k]
// CTA: 128 threads (4 warps), M-tile 64 (m16 per warp), N = 3*64 = 192.
// K-chunk 32 per smem stage. tf32 mma, fp32 accumulate.
// ---------------------------------------------------------------------------
#define PX_S 36   // 36 % 32 == 4 -> conflict-free fragment loads
#define PW_S 36

__global__ __launch_bounds__(128) void proj_kernel(
    const float* __restrict__ x,
    const float* __restrict__ Wq,
    const float* __restrict__ Wk,
    const float* __restrict__ Wv)
{
    __shared__ uint32_t Xs[64 * PX_S];
    __shared__ uint32_t Ws[192 * PW_S];

    const int tid  = threadIdx.x;
    const int warp = tid >> 5, lane = tid & 31;
    const int lr = lane >> 2, lc = lane & 3;
    const int m0 = blockIdx.x * 64;
    const int wrow = warp * 16;

    float c[24][4];
    #pragma unroll
    for (int i = 0; i < 24; i++)
        c[i][0] = c[i][1] = c[i][2] = c[i][3] = 0.f;

    for (int k0 = 0; k0 < DIN; k0 += 32) {
        __syncthreads();
        // X tile 64x32 -> tf32 smem
        #pragma unroll
        for (int it = 0; it < 4; it++) {
            int idx = tid + it * 128;          // 0..511
            int row = idx >> 3, c4 = idx & 7;
            float4 v = *(const float4*)&x[(size_t)(m0 + row) * DIN + k0 + c4 * 4];
            *(uint4*)&Xs[row * PX_S + c4 * 4] =
                make_uint4(f2tf(v.x), f2tf(v.y), f2tf(v.z), f2tf(v.w));
        }
        // W tile 192x32 (q rows 0-63, k rows 64-127, v rows 128-191)
        #pragma unroll
        for (int it = 0; it < 12; it++) {
            int idx = tid + it * 128;          // 0..1535
            int row = idx >> 3, c4 = idx & 7;
            const float* Wsel = (row < 64) ? Wq : (row < 128) ? Wk : Wv;
            int wr = row & 63;
            float4 v = *(const float4*)&Wsel[(size_t)wr * DIN + k0 + c4 * 4];
            *(uint4*)&Ws[row * PW_S + c4 * 4] =
                make_uint4(f2tf(v.x), f2tf(v.y), f2tf(v.z), f2tf(v.w));
        }
        __syncthreads();

        #pragma unroll
        for (int ks = 0; ks < 4; ks++) {
            int kk = ks * 8;
            uint32_t a0 = Xs[(wrow + lr) * PX_S + kk + lc];
            uint32_t a1 = Xs[(wrow + lr + 8) * PX_S + kk + lc];
            uint32_t a2 = Xs[(wrow + lr) * PX_S + kk + lc + 4];
            uint32_t a3 = Xs[(wrow + lr + 8) * PX_S + kk + lc + 4];
            #pragma unroll
            for (int nt = 0; nt < 24; nt++) {
                uint32_t b0 = Ws[(nt * 8 + lr) * PW_S + kk + lc];
                uint32_t b1 = Ws[(nt * 8 + lr) * PW_S + kk + lc + 4];
                mma_tf32(c[nt], a0, a1, a2, a3, b0, b1);
            }
        }
    }

    #pragma unroll
    for (int nt = 0; nt < 24; nt++) {
        float* g = (nt < 8) ? g_q : (nt < 16) ? g_k : g_v;
        int col = (nt & 7) * 8 + 2 * lc;
        size_t r0 = (size_t)(m0 + wrow + lr) * DOUT + col;
        *(float2*)&g[r0]             = make_float2(c[nt][0], c[nt][1]);
        *(float2*)&g[r0 + 8 * DOUT]  = make_float2(c[nt][2], c[nt][3]);
    }
}

// ---------------------------------------------------------------------------
// Flash attention, tf32 mma fragments. BM = BN = 64, D = 64.
// 128 threads (4 warps x m16). Q in registers (A-frags, pre-scaled with
// 0.125*log2e so softmax runs in exp2 space). K/V tiles tf32 in smem with
// conflict-free strides; P round-trips through per-warp smem.
// ---------------------------------------------------------------------------
#define KS_S 68   // 68 % 32 == 4
#define VS_S 72   // 72 % 32 == 8
#define PS_S 68
#define ATTN_SMEM_WORDS (64 * KS_S + 64 * VS_S + 4 * 16 * PS_S)
#define ATTN_SMEM_BYTES (ATTN_SMEM_WORDS * 4)   // 53248

__global__ __launch_bounds__(128, 3) void attn_kernel(float* __restrict__ out)
{
    extern __shared__ uint32_t sm[];
    uint32_t* Ks = sm;
    uint32_t* Vs = sm + 64 * KS_S;
    uint32_t* Ps = Vs + 64 * VS_S;

    const int tid  = threadIdx.x;
    const int warp = tid >> 5, lane = tid & 31;
    const int lr = lane >> 2, lc = lane & 3;

    const int bb = blockIdx.x & 3;
    const int qb = 63 - (blockIdx.x >> 2);   // biggest work first
    const int q0 = qb * 64;

    const float* __restrict__ qg = g_q + ((size_t)bb * SS + q0) * DOUT;
    const float* __restrict__ kg = g_k + (size_t)bb * SS * DOUT;
    const float* __restrict__ vg = g_v + (size_t)bb * SS * DOUT;

    uint32_t* Pw = Ps + warp * 16 * PS_S;

    // Q fragments, scaled by 1/sqrt(64) * log2(e) for exp2-space softmax
    const float qscale = 0.125f * 1.44269504f;
    uint32_t qa[8][4];
    #pragma unroll
    for (int kc = 0; kc < 8; kc++) {
        int col = kc * 8 + lc;
        qa[kc][0] = f2tf(qg[(warp * 16 + lr) * DOUT + col] * qscale);
        qa[kc][1] = f2tf(qg[(warp * 16 + lr + 8) * DOUT + col] * qscale);
        qa[kc][2] = f2tf(qg[(warp * 16 + lr) * DOUT + col + 4] * qscale);
        qa[kc][3] = f2tf(qg[(warp * 16 + lr + 8) * DOUT + col + 4] * qscale);
    }

    float o[8][4];
    #pragma unroll
    for (int nt = 0; nt < 8; nt++)
        o[nt][0] = o[nt][1] = o[nt][2] = o[nt][3] = 0.f;
    float m0r = -1e30f, m1r = -1e30f, l0r = 0.f, l1r = 0.f;

    for (int kb = 0; kb <= qb; kb++) {
        const int k0 = kb * 64;
        __syncthreads();   // all warps done with previous Ks/Vs
        #pragma unroll
        for (int it = 0; it < 8; it++) {
            int idx = tid + it * 128;
            int row = idx >> 4, c4 = idx & 15;
            float4 kv = *(const float4*)&kg[(size_t)(k0 + row) * DOUT + c4 * 4];
            *(uint4*)&Ks[row * KS_S + c4 * 4] =
                make_uint4(f2tf(kv.x), f2tf(kv.y), f2tf(kv.z), f2tf(kv.w));
            float4 vv = *(const float4*)&vg[(size_t)(k0 + row) * DOUT + c4 * 4];
            *(uint4*)&Vs[row * VS_S + c4 * 4] =
                make_uint4(f2tf(vv.x), f2tf(vv.y), f2tf(vv.z), f2tf(vv.w));
        }
        __syncthreads();

        // S = Q K^T  (per warp: 16x64)
        float sf[8][4];
        #pragma unroll
        for (int nt = 0; nt < 8; nt++)
            sf[nt][0] = sf[nt][1] = sf[nt][2] = sf[nt][3] = 0.f;
        #pragma unroll
        for (int kc = 0; kc < 8; kc++) {
            #pragma unroll
            for (int nt = 0; nt < 8; nt++) {
                uint32_t b0 = Ks[(nt * 8 + lr) * KS_S + kc * 8 + lc];
                uint32_t b1 = Ks[(nt * 8 + lr) * KS_S + kc * 8 + lc + 4];
                mma_tf32(sf[nt], qa[kc][0], qa[kc][1], qa[kc][2], qa[kc][3], b0, b1);
            }
        }

        // causal mask on the diagonal tile
        if (kb == qb) {
            int row0 = q0 + warp * 16 + lr;
            int row1 = row0 + 8;
            #pragma unroll
            for (int nt = 0; nt < 8; nt++) {
                int cb = k0 + nt * 8 + 2 * lc;
                if (cb     > row0) sf[nt][0] = -1e30f;
                if (cb + 1 > row0) sf[nt][1] = -1e30f;
                if (cb     > row1) sf[nt][2] = -1e30f;
                if (cb + 1 > row1) sf[nt][3] = -1e30f;
            }
        }

        // online softmax (exp2 space); quad = 4 lanes sharing a row
        float t0 = -1e30f, t1 = -1e30f;
        #pragma unroll
        for (int nt = 0; nt < 8; nt++) {
            t0 = fmaxf(t0, fmaxf(sf[nt][0], sf[nt][1]));
            t1 = fmaxf(t1, fmaxf(sf[nt][2], sf[nt][3]));
        }
        t0 = fmaxf(t0, __shfl_xor_sync(0xffffffffu, t0, 1));
        t0 = fmaxf(t0, __shfl_xor_sync(0xffffffffu, t0, 2));
        t1 = fmaxf(t1, __shfl_xor_sync(0xffffffffu, t1, 1));
        t1 = fmaxf(t1, __shfl_xor_sync(0xffffffffu, t1, 2));
        float mn0 = fmaxf(m0r, t0), mn1 = fmaxf(m1r, t1);
        float cor0 = ex2(m0r - mn0), cor1 = ex2(m1r - mn1);
        float rs0 = 0.f, rs1 = 0.f;
        #pragma unroll
        for (int nt = 0; nt < 8; nt++) {
            float p00 = ex2(sf[nt][0] - mn0), p01 = ex2(sf[nt][1] - mn0);
            float p10 = ex2(sf[nt][2] - mn1), p11 = ex2(sf[nt][3] - mn1);
            rs0 += p00 + p01; rs1 += p10 + p11;
            *(uint2*)&Pw[lr * PS_S + nt * 8 + 2 * lc] =
                make_uint2(f2tf(p00), f2tf(p01));
            *(uint2*)&Pw[(lr + 8) * PS_S + nt * 8 + 2 * lc] =
                make_uint2(f2tf(p10), f2tf(p11));
            o[nt][0] *= cor0; o[nt][1] *= cor0;
            o[nt][2] *= cor1; o[nt][3] *= cor1;
        }
        rs0 += __shfl_xor_sync(0xffffffffu, rs0, 1);
        rs0 += __shfl_xor_sync(0xffffffffu, rs0, 2);
        rs1 += __shfl_xor_sync(0xffffffffu, rs1, 1);
        rs1 += __shfl_xor_sync(0xffffffffu, rs1, 2);
        l0r = l0r * cor0 + rs0; l1r = l1r * cor1 + rs1;
        m0r = mn0; m1r = mn1;
        __syncwarp();   // P visible to all lanes of this warp

        // O += P V
        #pragma unroll
        for (int kc = 0; kc < 8; kc++) {
            uint32_t a0 = Pw[lr * PS_S + kc * 8 + lc];
            uint32_t a1 = Pw[(lr + 8) * PS_S + kc * 8 + lc];
            uint32_t a2 = Pw[lr * PS_S + kc * 8 + lc + 4];
            uint32_t a3 = Pw[(lr + 8) * PS_S + kc * 8 + lc + 4];
            #pragma unroll
            for (int nt = 0; nt < 8; nt++) {
                uint32_t b0 = Vs[(kc * 8 + lc) * VS_S + nt * 8 + lr];
                uint32_t b1 = Vs[(kc * 8 + lc + 4) * VS_S + nt * 8 + lr];
                mma_tf32(o[nt], a0, a1, a2, a3, b0, b1);
            }
        }
    }

    float inv0 = 1.f / l0r, inv1 = 1.f / l1r;
    #pragma unroll
    for (int nt = 0; nt < 8; nt++) {
        int col = nt * 8 + 2 * lc;
        size_t r0 = ((size_t)bb * SS + q0 + warp * 16 + lr) * DOUT + col;
        *(float2*)&out[r0]            = make_float2(o[nt][0] * inv0, o[nt][1] * inv0);
        *(float2*)&out[r0 + 8 * DOUT] = make_float2(o[nt][2] * inv1, o[nt][3] * inv1);
    }
}

// ---------------------------------------------------------------------------
extern "C" void kernel_launch(void* const* d_in, const int* in_sizes, int n_in,
                              void* d_out, int out_size)
{
    const float* x  = (const float*)d_in[0];
    const float* Wq = (const float*)d_in[1];
    const float* Wk = (const float*)d_in[2];
    const float* Wv = (const float*)d_in[3];
    float* out = (float*)d_out;

    proj_kernel<<<dim3((BB * SS) / 64), 128>>>(x, Wq, Wk, Wv);

    cudaFuncSetAttribute(attn_kernel,
                         cudaFuncAttributeMaxDynamicSharedMemorySize,
                         ATTN_SMEM_BYTES);
    attn_kernel<<<dim3(SS / 64 * BB), 128, ATTN_SMEM_BYTES>>>(out);
}

// round 3
// speedup vs baseline: 3.8184x; 1.0826x over previous
#include <cuda_runtime.h>
#include <cstdint>

#define BB 4
#define SS 4096
#define DIN 1024
#define DOUT 64

// Projected q,k,v stored as tf32 bit patterns (q pre-scaled by 0.125*log2e).
__device__ uint32_t g_q[BB * SS * DOUT];
__device__ uint32_t g_k[BB * SS * DOUT];
__device__ uint32_t g_v[BB * SS * DOUT];

// ---------------------------------------------------------------------------
// Helpers
// ---------------------------------------------------------------------------
__device__ __forceinline__ uint32_t f2tf(float f) {
    uint32_t r; asm("cvt.rna.tf32.f32 %0, %1;" : "=r"(r) : "f"(f)); return r;
}
__device__ __forceinline__ float ex2(float x) {
    float r; asm("ex2.approx.f32 %0, %1;" : "=f"(r) : "f"(x)); return r;
}
__device__ __forceinline__ void mma_tf32(float c[4],
    uint32_t a0, uint32_t a1, uint32_t a2, uint32_t a3,
    uint32_t b0, uint32_t b1)
{
    asm volatile(
        "mma.sync.aligned.m16n8k8.row.col.f32.tf32.tf32.f32 "
        "{%0,%1,%2,%3}, {%4,%5,%6,%7}, {%8,%9}, {%0,%1,%2,%3};"
        : "+f"(c[0]), "+f"(c[1]), "+f"(c[2]), "+f"(c[3])
        : "r"(a0), "r"(a1), "r"(a2), "r"(a3), "r"(b0), "r"(b1));
}
__device__ __forceinline__ void cpa16(uint32_t dst_smem, const void* src) {
    asm volatile("cp.async.cg.shared.global [%0], [%1], 16;"
                 :: "r"(dst_smem), "l"(src));
}
__device__ __forceinline__ void cpa_commit() {
    asm volatile("cp.async.commit_group;" ::: "memory");
}
__device__ __forceinline__ void cpa_wait0() {
    asm volatile("cp.async.wait_group 0;" ::: "memory");
}

// ---------------------------------------------------------------------------
// Fused QKV projection: tf32 mma, fp32 accumulate. Epilogue stores tf32 bits
// (q fold-scaled for exp2-space softmax).
// ---------------------------------------------------------------------------
#define PX_S 36
#define PW_S 36

__global__ __launch_bounds__(128) void proj_kernel(
    const float* __restrict__ x,
    const float* __restrict__ Wq,
    const float* __restrict__ Wk,
    const float* __restrict__ Wv)
{
    __shared__ uint32_t Xs[64 * PX_S];
    __shared__ uint32_t Ws[192 * PW_S];

    const int tid  = threadIdx.x;
    const int warp = tid >> 5, lane = tid & 31;
    const int lr = lane >> 2, lc = lane & 3;
    const int m0 = blockIdx.x * 64;
    const int wrow = warp * 16;

    float c[24][4];
    #pragma unroll
    for (int i = 0; i < 24; i++)
        c[i][0] = c[i][1] = c[i][2] = c[i][3] = 0.f;

    for (int k0 = 0; k0 < DIN; k0 += 32) {
        __syncthreads();
        #pragma unroll
        for (int it = 0; it < 4; it++) {
            int idx = tid + it * 128;
            int row = idx >> 3, c4 = idx & 7;
            float4 v = *(const float4*)&x[(size_t)(m0 + row) * DIN + k0 + c4 * 4];
            *(uint4*)&Xs[row * PX_S + c4 * 4] =
                make_uint4(f2tf(v.x), f2tf(v.y), f2tf(v.z), f2tf(v.w));
        }
        #pragma unroll
        for (int it = 0; it < 12; it++) {
            int idx = tid + it * 128;
            int row = idx >> 3, c4 = idx & 7;
            const float* Wsel = (row < 64) ? Wq : (row < 128) ? Wk : Wv;
            int wr = row & 63;
            float4 v = *(const float4*)&Wsel[(size_t)wr * DIN + k0 + c4 * 4];
            *(uint4*)&Ws[row * PW_S + c4 * 4] =
                make_uint4(f2tf(v.x), f2tf(v.y), f2tf(v.z), f2tf(v.w));
        }
        __syncthreads();

        #pragma unroll
        for (int ks = 0; ks < 4; ks++) {
            int kk = ks * 8;
            uint32_t a0 = Xs[(wrow + lr) * PX_S + kk + lc];
            uint32_t a1 = Xs[(wrow + lr + 8) * PX_S + kk + lc];
            uint32_t a2 = Xs[(wrow + lr) * PX_S + kk + lc + 4];
            uint32_t a3 = Xs[(wrow + lr + 8) * PX_S + kk + lc + 4];
            #pragma unroll
            for (int nt = 0; nt < 24; nt++) {
                uint32_t b0 = Ws[(nt * 8 + lr) * PW_S + kk + lc];
                uint32_t b1 = Ws[(nt * 8 + lr) * PW_S + kk + lc + 4];
                mma_tf32(c[nt], a0, a1, a2, a3, b0, b1);
            }
        }
    }

    const float qscale = 0.125f * 1.44269504f;   // 1/sqrt(64) * log2(e)
    #pragma unroll
    for (int nt = 0; nt < 24; nt++) {
        uint32_t* g = (nt < 8) ? g_q : (nt < 16) ? g_k : g_v;
        float s = (nt < 8) ? qscale : 1.0f;
        int col = (nt & 7) * 8 + 2 * lc;
        size_t r0 = (size_t)(m0 + wrow + lr) * DOUT + col;
        *(uint2*)&g[r0]            = make_uint2(f2tf(c[nt][0] * s), f2tf(c[nt][1] * s));
        *(uint2*)&g[r0 + 8 * DOUT] = make_uint2(f2tf(c[nt][2] * s), f2tf(c[nt][3] * s));
    }
}

// ---------------------------------------------------------------------------
// Flash attention, tf32 mma, cp.async double-buffered K/V pipeline.
// BM = BN = 64, D = 64, 128 threads (4 warps x m16).
// ---------------------------------------------------------------------------
#define KS_S 68
#define VS_S 72
#define PS_S 68
#define STAGE_WORDS (64 * KS_S + 64 * VS_S)
#define ATTN_SMEM_WORDS (2 * STAGE_WORDS + 4 * 16 * PS_S)
#define ATTN_SMEM_BYTES (ATTN_SMEM_WORDS * 4)   // 89088

__global__ __launch_bounds__(128, 2) void attn_kernel(float* __restrict__ out)
{
    extern __shared__ uint32_t sm[];
    // stage layout: [Ks0|Vs0|Ks1|Vs1|Ps]
    uint32_t* Ps = sm + 2 * STAGE_WORDS;

    const int tid  = threadIdx.x;
    const int warp = tid >> 5, lane = tid & 31;
    const int lr = lane >> 2, lc = lane & 3;

    const int bb = blockIdx.x & 3;
    const int qb = 63 - (blockIdx.x >> 2);   // biggest work first
    const int q0 = qb * 64;

    const uint32_t* __restrict__ qg = g_q + ((size_t)bb * SS + q0) * DOUT;
    const uint32_t* __restrict__ kg = g_k + (size_t)bb * SS * DOUT;
    const uint32_t* __restrict__ vg = g_v + (size_t)bb * SS * DOUT;

    uint32_t* Pw = Ps + warp * 16 * PS_S;
    const uint32_t ps_base = (uint32_t)__cvta_generic_to_shared(Ps);
    const uint32_t sm_base = (uint32_t)__cvta_generic_to_shared(sm);

    const int ldrow = tid >> 4;        // 0..7  (+8*it)
    const int ldc4  = (tid & 15) * 4;  // word offset within row

    // ---- prologue: stage Q into Ps region; stage K0/V0 into stage 0 ----
    #pragma unroll
    for (int it = 0; it < 8; it++) {
        int row = ldrow + it * 8;
        cpa16(ps_base + (row * PS_S + ldc4) * 4, qg + (size_t)row * DOUT + ldc4);
    }
    {
        uint32_t kdst = sm_base;
        uint32_t vdst = sm_base + 64 * KS_S * 4;
        #pragma unroll
        for (int it = 0; it < 8; it++) {
            int row = ldrow + it * 8;
            cpa16(kdst + (row * KS_S + ldc4) * 4, kg + (size_t)row * DOUT + ldc4);
            cpa16(vdst + (row * VS_S + ldc4) * 4, vg + (size_t)row * DOUT + ldc4);
        }
    }
    cpa_commit();
    cpa_wait0();
    __syncthreads();

    // Q fragments (already tf32 + scaled by proj)
    uint32_t qa[8][4];
    #pragma unroll
    for (int kc = 0; kc < 8; kc++) {
        qa[kc][0] = Pw[lr * PS_S + kc * 8 + lc];
        qa[kc][1] = Pw[(lr + 8) * PS_S + kc * 8 + lc];
        qa[kc][2] = Pw[lr * PS_S + kc * 8 + lc + 4];
        qa[kc][3] = Pw[(lr + 8) * PS_S + kc * 8 + lc + 4];
    }

    float o[8][4];
    #pragma unroll
    for (int nt = 0; nt < 8; nt++)
        o[nt][0] = o[nt][1] = o[nt][2] = o[nt][3] = 0.f;
    float m0r = -1e30f, m1r = -1e30f, l0r = 0.f, l1r = 0.f;

    for (int kb = 0; kb <= qb; kb++) {
        if (kb > 0) cpa_wait0();     // load kb complete (this thread's)
        __syncthreads();             // visible to all; prior compute done

        // issue prefetch of tile kb+1 into the other stage
        if (kb < qb) {
            const int kn = (kb + 1) * 64;
            uint32_t sb = sm_base + ((kb + 1) & 1) * STAGE_WORDS * 4;
            uint32_t kdst = sb;
            uint32_t vdst = sb + 64 * KS_S * 4;
            #pragma unroll
            for (int it = 0; it < 8; it++) {
                int row = ldrow + it * 8;
                cpa16(kdst + (row * KS_S + ldc4) * 4,
                      kg + (size_t)(kn + row) * DOUT + ldc4);
                cpa16(vdst + (row * VS_S + ldc4) * 4,
                      vg + (size_t)(kn + row) * DOUT + ldc4);
            }
            cpa_commit();
        }

        const uint32_t* Ks = sm + (kb & 1) * STAGE_WORDS;
        const uint32_t* Vs = Ks + 64 * KS_S;

        // S = Q K^T  (per warp: 16x64)
        float sf[8][4];
        #pragma unroll
        for (int nt = 0; nt < 8; nt++)
            sf[nt][0] = sf[nt][1] = sf[nt][2] = sf[nt][3] = 0.f;
        #pragma unroll
        for (int kc = 0; kc < 8; kc++) {
            #pragma unroll
            for (int nt = 0; nt < 8; nt++) {
                uint32_t b0 = Ks[(nt * 8 + lr) * KS_S + kc * 8 + lc];
                uint32_t b1 = Ks[(nt * 8 + lr) * KS_S + kc * 8 + lc + 4];
                mma_tf32(sf[nt], qa[kc][0], qa[kc][1], qa[kc][2], qa[kc][3], b0, b1);
            }
        }

        // causal mask on the diagonal tile
        if (kb == qb) {
            int row0 = q0 + warp * 16 + lr;
            int row1 = row0 + 8;
            const int k0 = kb * 64;
            #pragma unroll
            for (int nt = 0; nt < 8; nt++) {
                int cb = k0 + nt * 8 + 2 * lc;
                if (cb     > row0) sf[nt][0] = -1e30f;
                if (cb + 1 > row0) sf[nt][1] = -1e30f;
                if (cb     > row1) sf[nt][2] = -1e30f;
                if (cb + 1 > row1) sf[nt][3] = -1e30f;
            }
        }

        // online softmax (exp2 space); quad = 4 lanes share a row
        float t0 = -1e30f, t1 = -1e30f;
        #pragma unroll
        for (int nt = 0; nt < 8; nt++) {
            t0 = fmaxf(t0, fmaxf(sf[nt][0], sf[nt][1]));
            t1 = fmaxf(t1, fmaxf(sf[nt][2], sf[nt][3]));
        }
        t0 = fmaxf(t0, __shfl_xor_sync(0xffffffffu, t0, 1));
        t0 = fmaxf(t0, __shfl_xor_sync(0xffffffffu, t0, 2));
        t1 = fmaxf(t1, __shfl_xor_sync(0xffffffffu, t1, 1));
        t1 = fmaxf(t1, __shfl_xor_sync(0xffffffffu, t1, 2));
        float mn0 = fmaxf(m0r, t0), mn1 = fmaxf(m1r, t1);
        float cor0 = ex2(m0r - mn0), cor1 = ex2(m1r - mn1);
        float rs0 = 0.f, rs1 = 0.f;
        #pragma unroll
        for (int nt = 0; nt < 8; nt++) {
            float p00 = ex2(sf[nt][0] - mn0), p01 = ex2(sf[nt][1] - mn0);
            float p10 = ex2(sf[nt][2] - mn1), p11 = ex2(sf[nt][3] - mn1);
            rs0 += p00 + p01; rs1 += p10 + p11;
            *(uint2*)&Pw[lr * PS_S + nt * 8 + 2 * lc] =
                make_uint2(f2tf(p00), f2tf(p01));
            *(uint2*)&Pw[(lr + 8) * PS_S + nt * 8 + 2 * lc] =
                make_uint2(f2tf(p10), f2tf(p11));
            o[nt][0] *= cor0; o[nt][1] *= cor0;
            o[nt][2] *= cor1; o[nt][3] *= cor1;
        }
        rs0 += __shfl_xor_sync(0xffffffffu, rs0, 1);
        rs0 += __shfl_xor_sync(0xffffffffu, rs0, 2);
        rs1 += __shfl_xor_sync(0xffffffffu, rs1, 1);
        rs1 += __shfl_xor_sync(0xffffffffu, rs1, 2);
        l0r = l0r * cor0 + rs0; l1r = l1r * cor1 + rs1;
        m0r = mn0; m1r = mn1;
        __syncwarp();

        // O += P V
        #pragma unroll
        for (int kc = 0; kc < 8; kc++) {
            uint32_t a0 = Pw[lr * PS_S + kc * 8 + lc];
            uint32_t a1 = Pw[(lr + 8) * PS_S + kc * 8 + lc];
            uint32_t a2 = Pw[lr * PS_S + kc * 8 + lc + 4];
            uint32_t a3 = Pw[(lr + 8) * PS_S + kc * 8 + lc + 4];
            #pragma unroll
            for (int nt = 0; nt < 8; nt++) {
                uint32_t b0 = Vs[(kc * 8 + lc) * VS_S + nt * 8 + lr];
                uint32_t b1 = Vs[(kc * 8 + lc + 4) * VS_S + nt * 8 + lr];
                mma_tf32(o[nt], a0, a1, a2, a3, b0, b1);
            }
        }
    }

    float inv0 = 1.f / l0r, inv1 = 1.f / l1r;
    #pragma unroll
    for (int nt = 0; nt < 8; nt++) {
        int col = nt * 8 + 2 * lc;
        size_t r0 = ((size_t)bb * SS + q0 + warp * 16 + lr) * DOUT + col;
        *(float2*)&out[r0]            = make_float2(o[nt][0] * inv0, o[nt][1] * inv0);
        *(float2*)&out[r0 + 8 * DOUT] = make_float2(o[nt][2] * inv1, o[nt][3] * inv1);
    }
}

// ---------------------------------------------------------------------------
extern "C" void kernel_launch(void* const* d_in, const int* in_sizes, int n_in,
                              void* d_out, int out_size)
{
    const float* x  = (const float*)d_in[0];
    const float* Wq = (const float*)d_in[1];
    const float* Wk = (const float*)d_in[2];
    const float* Wv = (const float*)d_in[3];
    float* out = (float*)d_out;

    proj_kernel<<<dim3((BB * SS) / 64), 128>>>(x, Wq, Wk, Wv);

    cudaFuncSetAttribute(attn_kernel,
                         cudaFuncAttributeMaxDynamicSharedMemorySize,
                         ATTN_SMEM_BYTES);
    attn_kernel<<<dim3(SS / 64 * BB), 128, ATTN_SMEM_BYTES>>>(out);
}